// round 1
// baseline (speedup 1.0000x reference)
#include <cuda_runtime.h>
#include <math.h>

// ---------------- problem constants ----------------
#define M_SAMP 102400
#define NCOIL  12
#define NG     640          // oversampled grid
#define NH     320          // image size
#define NLINES (NCOIL*NG)   // 7680 FFT lines per direction

// Kaiser-Bessel: J=6, OSF=2, BETA = pi*sqrt((J*(OSF-0.5)/OSF)^2 - 0.8) = pi*sqrt(19.45)
#define PI_D 3.14159265358979323846
#define BETA_D (PI_D * 4.4102154142094819)   /* sqrt(19.45) */

// ---------------- scratch (static device memory; no runtime allocation) ----------------
__device__ float2 g_grid[NCOIL * NG * NG];   // 39.3 MB, L2-resident
__device__ float2 g_T128[64];                // exp(-2pi i k/128), k<64
__device__ float2 g_T640[512];               // exp(-2pi i e/640), e<512
__device__ float  g_S[NH];                   // apod reciprocal * 1/sqrt(640) per axis

// radix-5 twiddles W5^k = exp(-2pi i k/5)
__constant__ float2 c_W5[5] = {
    { 1.0f,                 0.0f                },
    { 0.30901699437494745f,-0.9510565162951535f },
    {-0.80901699437494745f,-0.5877852522924731f },
    {-0.80901699437494745f, 0.5877852522924731f },
    { 0.30901699437494745f, 0.9510565162951535f }
};

__device__ __forceinline__ float2 cmul(float2 a, float2 b) {
    return make_float2(a.x*b.x - a.y*b.y, a.x*b.y + a.y*b.x);
}

// ---------------- kernel 1: tables ----------------
__global__ void prep_kernel() {
    int t = threadIdx.x;
    if (t < 64) {
        double a = -2.0 * PI_D * (double)t / 128.0;
        g_T128[t] = make_float2((float)cos(a), (float)sin(a));
    }
    {
        double a = -2.0 * PI_D * (double)t / 640.0;
        g_T640[t] = make_float2((float)cos(a), (float)sin(a));
    }
    if (t < NH) {
        double n = (double)t - 160.0;
        double acc = 0.0;
        for (int js = -6; js <= 6; ++js) {
            double m = fabs((double)js) / 3.0;
            double kv = 0.0;
            if (m <= 1.0) {
                double arg = 1.0 - m*m; if (arg < 0.0) arg = 0.0;
                kv = cyl_bessel_i0(BETA_D * sqrt(arg)) / 6.0;
            }
            acc += kv * cos(2.0 * PI_D * (double)js * n / 640.0);
        }
        // reciprocal apod, with 1/sqrt(640) per axis (fft2 normalization 1/640 total)
        g_S[t] = (float)(1.0 / acc / sqrt(640.0));
    }
}

// ---------------- kernel 2: coil-combine * apod, zero-pad, ifftshift ----------------
__global__ void build_kernel(const float* __restrict__ imr, const float* __restrict__ imi,
                             const float* __restrict__ smr, const float* __restrict__ smi) {
    int idx = blockIdx.x * blockDim.x + threadIdx.x;   // over NCOIL*NG*NG (exact)
    int c   = idx / (NG*NG);
    int rem = idx - c * (NG*NG);
    int sh  = rem / NG;
    int sw  = rem - sh * NG;
    // inverse ifftshift mapping: padded index p = (s + NG/2) mod NG
    int ph = sh + NG/2; if (ph >= NG) ph -= NG;
    int pw = sw + NG/2; if (pw >= NG) pw -= NG;
    float2 val = make_float2(0.f, 0.f);
    if (ph >= 160 && ph < 480 && pw >= 160 && pw < 480) {
        int h = ph - 160, w = pw - 160;
        int ii = h * NH + w;
        float ir = imr[ii], ij = imi[ii];
        int si = c * NH * NH + ii;
        float sr = smr[si], sj = smi[si];
        float sc = g_S[h] * g_S[w];
        val.x = (ir*sr - ij*sj) * sc;
        val.y = (ir*sj + ij*sr) * sc;
    }
    g_grid[idx] = val;
}

// ---------------- kernels 3/4: 640-point FFT lines (640 = 5 * 128) ----------------
// Decomposition: n = 5*n1 + n2, k = k1 + 128*k2.
// Five 128-pt Stockham FFTs over n1, twiddle W640^(n2*k1), then radix-5 over n2.
template<int LINES, int STRIDE>
__global__ void fft640_kernel() {
    __shared__ float2 bufA[LINES][640];
    __shared__ float2 bufB[LINES][640];
    int lane = threadIdx.x & 127;
    int ln   = threadIdx.x >> 7;
    int line = blockIdx.x * LINES + ln;

    float2* base;
    if (STRIDE == 1) {
        base = g_grid + line * NG;                    // row: coil*640+row, contiguous
    } else {
        int coil = line / NG;
        int col  = line - coil * NG;                  // 4 adjacent cols per CTA -> sector reuse
        base = g_grid + coil * (NG*NG) + col;
    }

    float2* A = bufA[ln];
    float2* B = bufB[ln];

    // stage load (coalesced for rows), then decimate: A[j*128 + n1] = x[5*n1 + j]
    #pragma unroll
    for (int q = 0; q < 5; ++q) B[lane + 128*q] = base[(lane + 128*q) * STRIDE];
    __syncthreads();
    #pragma unroll
    for (int j = 0; j < 5; ++j) A[j*128 + lane] = B[5*lane + j];
    __syncthreads();

    // 7 radix-2 Stockham stages on 5 independent 128-pt FFTs
    float2 *X = A, *Y = B;
    #pragma unroll
    for (int st = 0; st < 7; ++st) {
        int s = 1 << st;
        #pragma unroll
        for (int bi = 0; bi < 3; ++bi) {
            int b = lane + 128*bi;
            if (b < 320) {
                int sub = b >> 6;
                int bb  = b & 63;               // = q + s*p
                int q   = bb & (s - 1);
                float2 a  = X[sub*128 + bb];
                float2 cc = X[sub*128 + bb + 64];
                float2 w  = g_T128[(bb >> st) << st];
                int i0 = ((bb >> st) << (st + 1)) | q;
                float2 sum = make_float2(a.x + cc.x, a.y + cc.y);
                float2 dif = make_float2(a.x - cc.x, a.y - cc.y);
                float2 dw  = cmul(dif, w);
                Y[sub*128 + i0]     = sum;
                Y[sub*128 + i0 + s] = dw;
            }
        }
        __syncthreads();
        float2* t = X; X = Y; Y = t;
    }

    // twiddle + radix-5 combine; output index k1 + 128*k2 (natural order)
    float2 v[5];
    #pragma unroll
    for (int j = 0; j < 5; ++j) {
        v[j] = cmul(X[j*128 + lane], g_T640[j * lane]);
    }
    #pragma unroll
    for (int k2 = 0; k2 < 5; ++k2) {
        float2 acc = v[0];
        #pragma unroll
        for (int j = 1; j < 5; ++j) {
            float2 w5 = c_W5[(j * k2) % 5];
            acc.x += v[j].x * w5.x - v[j].y * w5.y;
            acc.y += v[j].x * w5.y + v[j].y * w5.x;
        }
        base[(lane + 128*k2) * STRIDE] = acc;
    }
}

// ---------------- kernel 5: Kaiser-Bessel interpolation (gather) ----------------
__global__ void interp_kernel(const float* __restrict__ kt, float2* __restrict__ out) {
    int m = blockIdx.x * blockDim.x + threadIdx.x;
    if (m >= M_SAMP) return;

    const float BETA_F = (float)BETA_D;
    const float G_OVER_2PI = 101.85916357881302f;   // 640/(2pi)

    float om1 = kt[m];
    float om2 = kt[M_SAMP + m];

    float wx[6], wy[6];
    int ixo[6], iyo[6];

    // axis 1 (rows)
    {
        float t = om1 * G_OVER_2PI;
        if (t < 0.f) t += 640.f;
        int ib = (int)floorf(t);
        #pragma unroll
        for (int i = 0; i < 6; ++i) {
            int k = ib + i - 2;
            float u = t - (float)k;
            float mm = fabsf(u) * (1.f/3.f);
            float arg = fmaxf(1.f - mm*mm, 0.f);
            wx[i] = (mm <= 1.f) ? cyl_bessel_i0f(BETA_F * sqrtf(arg)) * (1.f/6.f) : 0.f;
            if (k < 0) k += 640; else if (k >= 640) k -= 640;
            ixo[i] = k * NG;
        }
    }
    // axis 2 (cols)
    {
        float t = om2 * G_OVER_2PI;
        if (t < 0.f) t += 640.f;
        int ib = (int)floorf(t);
        #pragma unroll
        for (int i = 0; i < 6; ++i) {
            int k = ib + i - 2;
            float u = t - (float)k;
            float mm = fabsf(u) * (1.f/3.f);
            float arg = fmaxf(1.f - mm*mm, 0.f);
            wy[i] = (mm <= 1.f) ? cyl_bessel_i0f(BETA_F * sqrtf(arg)) * (1.f/6.f) : 0.f;
            if (k < 0) k += 640; else if (k >= 640) k -= 640;
            iyo[i] = k;
        }
    }

    // combined 6x6 weights in registers
    float w36[36];
    #pragma unroll
    for (int i = 0; i < 6; ++i)
        #pragma unroll
        for (int j = 0; j < 6; ++j)
            w36[i*6 + j] = wx[i] * wy[j];

    for (int c = 0; c < NCOIL; ++c) {
        const float2* gp = g_grid + c * (NG*NG);
        float re = 0.f, im = 0.f;
        #pragma unroll
        for (int i = 0; i < 6; ++i) {
            const float2* rp = gp + ixo[i];
            #pragma unroll
            for (int j = 0; j < 6; ++j) {
                float2 gv = __ldg(&rp[iyo[j]]);
                float w = w36[i*6 + j];
                re = fmaf(gv.x, w, re);
                im = fmaf(gv.y, w, im);
            }
        }
        out[c * M_SAMP + m] = make_float2(re, im);   // [B,C,M,2] layout
    }
}

// ---------------- launch ----------------
extern "C" void kernel_launch(void* const* d_in, const int* in_sizes, int n_in,
                              void* d_out, int out_size) {
    const float* imr = (const float*)d_in[0];
    const float* imi = (const float*)d_in[1];
    const float* smr = (const float*)d_in[2];
    const float* smi = (const float*)d_in[3];
    const float* kt  = (const float*)d_in[4];

    prep_kernel<<<1, 512>>>();
    build_kernel<<<(NCOIL*NG*NG) / 256, 256>>>(imr, imi, smr, smi);
    fft640_kernel<2, 1>  <<<NLINES / 2, 256>>>();   // rows
    fft640_kernel<4, NG> <<<NLINES / 4, 512>>>();   // cols (4 adjacent cols/CTA)
    interp_kernel<<<(M_SAMP + 127) / 128, 128>>>(kt, (float2*)d_out);
}

// round 2
// speedup vs baseline: 1.4375x; 1.4375x over previous
#include <cuda_runtime.h>
#include <math.h>

// ---------------- problem constants ----------------
#define M_SAMP 102400
#define NCOIL  12
#define NG     640          // oversampled grid
#define NH     320          // image size

#define PI_D 3.14159265358979323846
#define BETA_D (PI_D * 4.4102154142094819)   /* pi*sqrt(19.45) */

// padded smem indexing to avoid strided-write bank conflicts
#define PADN 800
#define PHYS(i) ((i) + ((i) >> 2))

// ---------------- static device scratch ----------------
__device__ float2 g_grid [NCOIL * NG * NG];  // pass-A output [c][row][colfreq]
__device__ float2 g_grid2[NCOIL * NG * NG];  // transposed / final [c][colfreq][rowfreq]
__device__ float2 g_T128[96];                // W128^k, k<96
__device__ float2 g_T640[512];               // W640^e, e<512
__device__ float  g_S[NH];                   // apod reciprocal * 1/sqrt(640)

__constant__ float2 c_W5[5] = {
    { 1.0f,                 0.0f                },
    { 0.30901699437494745f,-0.9510565162951535f },
    {-0.80901699437494745f,-0.5877852522924731f },
    {-0.80901699437494745f, 0.5877852522924731f },
    { 0.30901699437494745f, 0.9510565162951535f }
};

__device__ __forceinline__ float2 cmul(float2 a, float2 b) {
    return make_float2(a.x*b.x - a.y*b.y, a.x*b.y + a.y*b.x);
}

// ---------------- kernel 1: tables ----------------
__global__ void prep_kernel() {
    int t = threadIdx.x;
    if (t < 96) {
        double a = -2.0 * PI_D * (double)t / 128.0;
        g_T128[t] = make_float2((float)cos(a), (float)sin(a));
    }
    {
        double a = -2.0 * PI_D * (double)t / 640.0;
        g_T640[t] = make_float2((float)cos(a), (float)sin(a));
    }
    if (t < NH) {
        double n = (double)t - 160.0;
        double acc = 0.0;
        for (int js = -6; js <= 6; ++js) {
            double m = fabs((double)js) / 3.0;
            double kv = 0.0;
            if (m <= 1.0) {
                double arg = 1.0 - m*m; if (arg < 0.0) arg = 0.0;
                kv = cyl_bessel_i0(BETA_D * sqrt(arg)) / 6.0;
            }
            acc += kv * cos(2.0 * PI_D * (double)js * n / 640.0);
        }
        g_S[t] = (float)(1.0 / acc / sqrt(640.0));
    }
}

// ---------------- radix-4 Stockham work item (fused pair of radix-2 stages) ----------------
__device__ __forceinline__ void r4_item(const float2* X, float2* Y, int w, int s) {
    int sub = w >> 5;
    int bb  = w & 31;
    int q   = bb & (s - 1);
    int ps  = bb - q;            // p*s
    int bi  = sub * 128;
    float2 x0 = X[PHYS(bi + bb)];
    float2 x1 = X[PHYS(bi + bb + 32)];
    float2 x2 = X[PHYS(bi + bb + 64)];
    float2 x3 = X[PHYS(bi + bb + 96)];
    float2 A = make_float2(x0.x + x2.x, x0.y + x2.y);
    float2 B = make_float2(x1.x + x3.x, x1.y + x3.y);
    float2 C = make_float2(x0.x - x2.x, x0.y - x2.y);
    float2 D = make_float2(x1.x - x3.x, x1.y - x3.y);
    float2 E = make_float2(D.y, -D.x);              // -i*D
    float2 w1 = g_T128[ps];
    float2 w2 = g_T128[2*ps];
    float2 w3 = g_T128[3*ps];
    int o = bi + 4*ps + q;
    Y[PHYS(o)]       = make_float2(A.x + B.x, A.y + B.y);
    Y[PHYS(o + s)]   = cmul(make_float2(C.x + E.x, C.y + E.y), w1);
    Y[PHYS(o + 2*s)] = cmul(make_float2(A.x - B.x, A.y - B.y), w2);
    Y[PHYS(o + 3*s)] = cmul(make_float2(C.x - E.x, C.y - E.y), w3);
}

// 640-pt FFT on data already loaded (decimated) into A; result stored to gout (natural order)
__device__ __forceinline__ void fft_line(float2* A, float2* B, int lane, float2* gout) {
    float2 *X = A, *Y = B;
    #pragma unroll
    for (int st = 0; st < 3; ++st) {
        int s = 1 << (2*st);
        r4_item(X, Y, lane, s);
        if (lane < 32) r4_item(X, Y, 128 + lane, s);
        __syncthreads();
        float2* t = X; X = Y; Y = t;
    }
    // fused final radix-2 (s=64, no twiddle) + twiddle + radix-5 combine
    int l6 = lane & 63;
    float2 v[5];
    #pragma unroll
    for (int j = 0; j < 5; ++j) {
        float2 u = X[PHYS(j*128 + l6)];
        float2 w = X[PHYS(j*128 + l6 + 64)];
        float2 f = (lane < 64) ? make_float2(u.x + w.x, u.y + w.y)
                               : make_float2(u.x - w.x, u.y - w.y);
        v[j] = cmul(f, g_T640[j * lane]);
    }
    #pragma unroll
    for (int k2 = 0; k2 < 5; ++k2) {
        float2 acc = v[0];
        #pragma unroll
        for (int j = 1; j < 5; ++j) {
            float2 w5 = c_W5[(j * k2) % 5];
            acc.x += v[j].x * w5.x - v[j].y * w5.y;
            acc.y += v[j].x * w5.y + v[j].y * w5.x;
        }
        gout[lane + 128 * k2] = acc;
    }
}

// ---------------- pass A: fused (coil-combine * apod, pad, ifftshift) + row FFT ----------------
// only the 320 nonzero rows per coil are processed (others never read downstream)
__global__ void fftA_kernel(const float* __restrict__ imr, const float* __restrict__ imi,
                            const float* __restrict__ smr, const float* __restrict__ smi) {
    __shared__ float2 SA[2][PADN];
    __shared__ float2 SB[2][PADN];
    int tid  = threadIdx.x;
    int lane = tid & 127;
    int ln   = tid >> 7;
    int idx  = blockIdx.x * 2 + ln;          // [0, 12*320)
    int coil = idx / NH;
    int rr   = idx - coil * NH;
    int r    = (rr < 160) ? rr : rr + 320;   // nonzero padded row
    int h    = (rr < 160) ? rr + 160 : rr - 160;
    float2* gout = g_grid + (coil * NG + r) * NG;

    float sh_ = g_S[h];
    const float* smr_c = smr + coil * (NH*NH);
    const float* smi_c = smi + coil * (NH*NH);

    #pragma unroll
    for (int j = 0; j < 5; ++j) {
        int sc = 5 * lane + j;               // shifted column index
        float2 val = make_float2(0.f, 0.f);
        int w = -1;
        if (sc < 160) w = sc + 160;
        else if (sc >= 480) w = sc - 480;
        if (w >= 0) {
            int ii = h * NH + w;
            float ir = imr[ii], ij = imi[ii];
            float sr = smr_c[ii], sj = smi_c[ii];
            float sca = sh_ * g_S[w];
            val.x = (ir*sr - ij*sj) * sca;
            val.y = (ir*sj + ij*sr) * sca;
        }
        SA[ln][PHYS(j*128 + lane)] = val;    // decimated: A[j*128+n1] = x[5*n1+j]
    }
    __syncthreads();
    fft_line(SA[ln], SB[ln], lane, gout);
}

// ---------------- transpose (nonzero rows only): g_grid[c][r][k] -> g_grid2[c][k][r] ----------------
__global__ void transpose_kernel() {
    __shared__ float2 tile[32][33];
    int c  = blockIdx.z;
    int k0 = blockIdx.x * 32;
    int rt = blockIdx.y;
    int r0 = ((rt < 5) ? rt : rt + 10) * 32;  // rows [0,160) u [480,640)
    const float2* src = g_grid  + c * (NG*NG);
    float2*       dst = g_grid2 + c * (NG*NG);
    int tx = threadIdx.x, ty = threadIdx.y;
    #pragma unroll
    for (int yy = 0; yy < 4; ++yy)
        tile[ty + 8*yy][tx] = src[(r0 + ty + 8*yy) * NG + k0 + tx];
    __syncthreads();
    #pragma unroll
    for (int yy = 0; yy < 4; ++yy)
        dst[(k0 + ty + 8*yy) * NG + r0 + tx] = tile[tx][ty + 8*yy];
}

// ---------------- pass B: row FFT over transposed grid (in-place), middle half known zero ----------------
__global__ void fftB_kernel() {
    __shared__ float2 SA[2][PADN];
    __shared__ float2 SB[2][PADN];
    int tid  = threadIdx.x;
    int lane = tid & 127;
    int ln   = tid >> 7;
    int line = blockIdx.x * 2 + ln;          // [0, 12*640)
    float2* gio = g_grid2 + line * NG;

    #pragma unroll
    for (int j = 0; j < 5; ++j) {
        int sc = 5 * lane + j;
        float2 val = make_float2(0.f, 0.f);
        if (sc < 160 || sc >= 480) val = __ldg(&gio[sc]);
        SA[ln][PHYS(j*128 + lane)] = val;
    }
    __syncthreads();
    fft_line(SA[ln], SB[ln], lane, gio);
}

// ---------------- Kaiser-Bessel interpolation: one warp per sample ----------------
__global__ void interp_kernel(const float* __restrict__ kt, float2* __restrict__ out) {
    int m    = blockIdx.x * 8 + (threadIdx.x >> 5);
    int lane = threadIdx.x & 31;

    const float BETA_F = (float)BETA_D;
    const float G2PI   = 101.85916357881302f;   // 640/(2*pi)
    const unsigned FULL = 0xffffffffu;

    float om1 = __ldg(kt + m);
    float om2 = __ldg(kt + M_SAMP + m);
    float tx = om1 * G2PI; if (tx < 0.f) tx += 640.f;
    float ty = om2 * G2PI; if (ty < 0.f) ty += 640.f;
    float bx = floorf(tx), by = floorf(ty);

    int i1 = lane % 6, j1 = lane / 6;           // tap (i1,j1) for taps 0..31

    // KB kernel values computed by lanes 0..11 (6 x-taps, 6 y-taps), broadcast by shuffle
    float kv = 0.f;
    if (lane < 12) {
        bool isx = lane < 6;
        int  sl  = isx ? lane : lane - 6;
        float t  = isx ? tx : ty;
        float b  = isx ? bx : by;
        float u  = t - (b + (float)(sl - 2));
        float mm = fabsf(u) * (1.f/3.f);
        float arg = fmaxf(1.f - mm*mm, 0.f);
        kv = (mm <= 1.f) ? cyl_bessel_i0f(BETA_F * sqrtf(arg)) * (1.f/6.f) : 0.f;
    }
    float w1 = __shfl_sync(FULL, kv, i1) * __shfl_sync(FULL, kv, 6 + j1);
    bool has2 = lane < 4;                        // taps 32..35: (i=lane+2, j=5)
    int  i2   = has2 ? lane + 2 : 0;
    float w2  = __shfl_sync(FULL, kv, i2) * __shfl_sync(FULL, kv, 11);

    int bxi = (int)bx, byi = (int)by;
    int kx1 = bxi + i1 - 2; if (kx1 < 0) kx1 += NG; else if (kx1 >= NG) kx1 -= NG;
    int ky1 = byi + j1 - 2; if (ky1 < 0) ky1 += NG; else if (ky1 >= NG) ky1 -= NG;
    int o1  = ky1 * NG + kx1;                    // g_grid2 layout: [y][x], x contiguous
    int kx2 = bxi + i2 - 2; if (kx2 < 0) kx2 += NG; else if (kx2 >= NG) kx2 -= NG;
    int ky5 = byi + 3;      if (ky5 >= NG) ky5 -= NG;
    int o2  = ky5 * NG + kx2;

    #pragma unroll
    for (int c = 0; c < NCOIL; ++c) {
        const float2* gp = g_grid2 + c * (NG*NG);
        float2 a = __ldg(gp + o1);
        float re = w1 * a.x;
        float im = w1 * a.y;
        if (has2) {
            float2 bv = __ldg(gp + o2);
            re = fmaf(w2, bv.x, re);
            im = fmaf(w2, bv.y, im);
        }
        #pragma unroll
        for (int off = 16; off; off >>= 1) {
            re += __shfl_xor_sync(FULL, re, off);
            im += __shfl_xor_sync(FULL, im, off);
        }
        if (lane == 0) out[c * M_SAMP + m] = make_float2(re, im);
    }
}

// ---------------- launch ----------------
extern "C" void kernel_launch(void* const* d_in, const int* in_sizes, int n_in,
                              void* d_out, int out_size) {
    const float* imr = (const float*)d_in[0];
    const float* imi = (const float*)d_in[1];
    const float* smr = (const float*)d_in[2];
    const float* smi = (const float*)d_in[3];
    const float* kt  = (const float*)d_in[4];

    prep_kernel<<<1, 512>>>();
    fftA_kernel<<<(NCOIL * NH) / 2, 256>>>(imr, imi, smr, smi);   // 1920 CTAs, nonzero rows only
    transpose_kernel<<<dim3(20, 10, NCOIL), dim3(32, 8)>>>();
    fftB_kernel<<<(NCOIL * NG) / 2, 256>>>();                     // 3840 CTAs
    interp_kernel<<<M_SAMP / 8, 256>>>(kt, (float2*)d_out);
}

// round 4
// speedup vs baseline: 2.7916x; 1.9420x over previous
#include <cuda_runtime.h>
#include <math.h>

// ---------------- problem constants ----------------
#define M_SAMP 102400
#define NCOIL  12
#define NG     640          // oversampled grid
#define NH     320          // image size

#define PI_D 3.14159265358979323846
#define BETA_D (PI_D * 4.4102154142094819)   /* pi*sqrt(19.45) */

// padded smem indexing to avoid strided bank conflicts
#define PADN 800
#define PHYS(i) ((i) + ((i) >> 2))

// ---------------- static device scratch ----------------
__device__ float2 g_final[NG * NG * NCOIL];  // final grid [k2][k1][c], coil innermost (39.3MB)
__device__ float2 g_mid  [NCOIL * NG * NG];  // after pass A: [c][k2][r]
__device__ float2 g_T128[96];                // W128^k, k<96
__device__ float2 g_T640[512];               // W640^e, e<512
__device__ float  g_S[NH];                   // apod reciprocal * 1/sqrt(640)

__constant__ float2 c_W5[5] = {
    { 1.0f,                 0.0f                },
    { 0.30901699437494745f,-0.9510565162951535f },
    {-0.80901699437494745f,-0.5877852522924731f },
    {-0.80901699437494745f, 0.5877852522924731f },
    { 0.30901699437494745f, 0.9510565162951535f }
};

__device__ __forceinline__ float2 cmul(float2 a, float2 b) {
    return make_float2(a.x*b.x - a.y*b.y, a.x*b.y + a.y*b.x);
}

// ---------------- kernel 1: tables ----------------
__global__ void prep_kernel() {
    int t = threadIdx.x;   // 640 threads
    if (t < 96) {
        double a = -2.0 * PI_D * (double)t / 128.0;
        g_T128[t] = make_float2((float)cos(a), (float)sin(a));
    }
    if (t < 512) {
        double a = -2.0 * PI_D * (double)t / 640.0;
        g_T640[t] = make_float2((float)cos(a), (float)sin(a));
    }
    if (t < NH) {
        float n = (float)t - 160.0f;
        float acc = 0.0f;
        #pragma unroll
        for (int js = -6; js <= 6; ++js) {
            float m = fabsf((float)js) * (1.0f/3.0f);
            float kv = 0.0f;
            if (m <= 1.0f) {
                float arg = fmaxf(1.0f - m*m, 0.0f);
                kv = cyl_bessel_i0f((float)BETA_D * sqrtf(arg)) * (1.0f/6.0f);
            }
            acc += kv * cosf(2.0f * (float)PI_D * (float)js * n / 640.0f);
        }
        g_S[t] = 1.0f / acc * 0.039528470752104741f;   // 1/sqrt(640)
    }
}

// ---------------- radix-4 Stockham work item ----------------
__device__ __forceinline__ void r4_item(const float2* X, float2* Y, int w, int s) {
    int sub = w >> 5;
    int bb  = w & 31;
    int q   = bb & (s - 1);
    int ps  = bb - q;            // p*s
    int bi  = sub * 128;
    float2 x0 = X[PHYS(bi + bb)];
    float2 x1 = X[PHYS(bi + bb + 32)];
    float2 x2 = X[PHYS(bi + bb + 64)];
    float2 x3 = X[PHYS(bi + bb + 96)];
    float2 A = make_float2(x0.x + x2.x, x0.y + x2.y);
    float2 B = make_float2(x1.x + x3.x, x1.y + x3.y);
    float2 C = make_float2(x0.x - x2.x, x0.y - x2.y);
    float2 D = make_float2(x1.x - x3.x, x1.y - x3.y);
    float2 E = make_float2(D.y, -D.x);              // -i*D
    float2 w1 = g_T128[ps];
    float2 w2 = g_T128[2*ps];
    float2 w3 = g_T128[3*ps];
    int o = bi + 4*ps + q;
    Y[PHYS(o)]       = make_float2(A.x + B.x, A.y + B.y);
    Y[PHYS(o + s)]   = cmul(make_float2(C.x + E.x, C.y + E.y), w1);
    Y[PHYS(o + 2*s)] = cmul(make_float2(A.x - B.x, A.y - B.y), w2);
    Y[PHYS(o + 3*s)] = cmul(make_float2(C.x - E.x, C.y - E.y), w3);
}

// 640-pt FFT on decimated data in A; store result k at gout[k*STRIDE]
__device__ __forceinline__ void fft_line(float2* A, float2* B, int lane,
                                         float2* gout, int stride) {
    float2 *X = A, *Y = B;
    #pragma unroll
    for (int st = 0; st < 3; ++st) {
        int s = 1 << (2*st);
        r4_item(X, Y, lane, s);
        if (lane < 32) r4_item(X, Y, 128 + lane, s);
        __syncthreads();
        float2* t = X; X = Y; Y = t;
    }
    // fused final radix-2 (s=64) + twiddle + radix-5 combine
    int l6 = lane & 63;
    float2 v[5];
    #pragma unroll
    for (int j = 0; j < 5; ++j) {
        float2 u = X[PHYS(j*128 + l6)];
        float2 w = X[PHYS(j*128 + l6 + 64)];
        float2 f = (lane < 64) ? make_float2(u.x + w.x, u.y + w.y)
                               : make_float2(u.x - w.x, u.y - w.y);
        v[j] = cmul(f, g_T640[j * lane]);
    }
    #pragma unroll
    for (int k2 = 0; k2 < 5; ++k2) {
        float2 acc = v[0];
        #pragma unroll
        for (int j = 1; j < 5; ++j) {
            float2 w5 = c_W5[(j * k2) % 5];
            acc.x += v[j].x * w5.x - v[j].y * w5.y;
            acc.y += v[j].x * w5.y + v[j].y * w5.x;
        }
        gout[(lane + 128 * k2) * stride] = acc;
    }
}

// ---------------- pass A: fused build + column FFT + transposed store ----------------
// input: nonzero padded rows only; output g_mid[c][k2][r] (scatter, stride NG)
__global__ void fftA_kernel(const float* __restrict__ imr, const float* __restrict__ imi,
                            const float* __restrict__ smr, const float* __restrict__ smi) {
    __shared__ float2 SA[2][PADN];
    __shared__ float2 SB[2][PADN];
    int tid  = threadIdx.x;
    int lane = tid & 127;
    int ln   = tid >> 7;
    int idx  = blockIdx.x * 2 + ln;          // [0, 12*320)
    int coil = idx / NH;
    int rr   = idx - coil * NH;
    int r    = (rr < 160) ? rr : rr + 320;   // nonzero padded row index
    int h    = (rr < 160) ? rr + 160 : rr - 160;

    float sh_ = g_S[h];
    const float* smr_c = smr + coil * (NH*NH);
    const float* smi_c = smi + coil * (NH*NH);

    #pragma unroll
    for (int j = 0; j < 5; ++j) {
        int sc = 5 * lane + j;               // shifted column index
        float2 val = make_float2(0.f, 0.f);
        int w = -1;
        if (sc < 160) w = sc + 160;
        else if (sc >= 480) w = sc - 480;
        if (w >= 0) {
            int ii = h * NH + w;
            float ir = imr[ii], ij = imi[ii];
            float sr = smr_c[ii], sj = smi_c[ii];
            float sca = sh_ * g_S[w];
            val.x = (ir*sr - ij*sj) * sca;
            val.y = (ir*sj + ij*sr) * sca;
        }
        SA[ln][PHYS(j*128 + lane)] = val;    // decimated: A[j*128+n1] = x[5*n1+j]
    }
    __syncthreads();
    // transposed store: g_mid[(coil*NG + k2)*NG + r]
    fft_line(SA[ln], SB[ln], lane, g_mid + coil * (NG*NG) + r, NG);
}

// ---------------- pass B: row FFT over g_mid lines, coil-interleaved store ----------------
__global__ void fftB_kernel() {
    __shared__ float2 SA[2][PADN];
    __shared__ float2 SB[2][PADN];
    int tid  = threadIdx.x;
    int lane = tid & 127;
    int ln   = tid >> 7;
    int line = blockIdx.x * 2 + ln;          // [0, 12*640)
    int coil = line / NG;
    int k2   = line - coil * NG;
    const float2* gin = g_mid + (coil * NG + k2) * NG;

    #pragma unroll
    for (int j = 0; j < 5; ++j) {
        int sc = 5 * lane + j;
        float2 val = make_float2(0.f, 0.f);
        if (sc < 160 || sc >= 480) val = __ldg(&gin[sc]);
        SA[ln][PHYS(j*128 + lane)] = val;
    }
    __syncthreads();
    // store: g_final[(k2*NG + k1)*NCOIL + coil], stride NCOIL over k1
    fft_line(SA[ln], SB[ln], lane, g_final + k2 * (NG*NCOIL) + coil, NCOIL);
}

// ---------------- KB interpolation: warp per sample, lane = (coil, half) ----------------
__global__ void interp_kernel(const float* __restrict__ kt, float2* __restrict__ out) {
    int m    = blockIdx.x * 8 + (threadIdx.x >> 5);
    int lane = threadIdx.x & 31;

    const float BETA_F = (float)BETA_D;
    const float G2PI   = 101.85916357881302f;   // 640/(2*pi)
    const unsigned FULL = 0xffffffffu;

    float om1 = __ldg(kt + m);
    float om2 = __ldg(kt + M_SAMP + m);
    float tx = om1 * G2PI; if (tx < 0.f) tx += 640.f;
    float ty = om2 * G2PI; if (ty < 0.f) ty += 640.f;
    float bx = floorf(tx), by = floorf(ty);

    // KB kernel values: lanes 0..5 -> wx taps, lanes 6..11 -> wy taps
    float kv = 0.f;
    if (lane < 12) {
        bool isx = lane < 6;
        int  sl  = isx ? lane : lane - 6;
        float t  = isx ? tx : ty;
        float b  = isx ? bx : by;
        float u  = t - (b + (float)(sl - 2));
        float mm = fabsf(u) * (1.f/3.f);
        float arg = fmaxf(1.f - mm*mm, 0.f);
        kv = (mm <= 1.f) ? cyl_bessel_i0f(BETA_F * sqrtf(arg)) * (1.f/6.f) : 0.f;
    }

    int c   = lane >> 1;          // coil 0..15 (12 active)
    int h   = lane & 1;           // x-tap half: taps h*3..h*3+2
    bool act = (lane < 24);

    float wxl[3], wyl[6];
    #pragma unroll
    for (int t = 0; t < 3; ++t) wxl[t] = __shfl_sync(FULL, kv, h*3 + t);
    #pragma unroll
    for (int j = 0; j < 6; ++j) wyl[j] = __shfl_sync(FULL, kv, 6 + j);

    int bxi = (int)bx, byi = (int)by;
    int xo[3], yo[6];
    #pragma unroll
    for (int t = 0; t < 3; ++t) {
        int k = bxi + (h*3 + t) - 2;
        if (k < 0) k += NG; else if (k >= NG) k -= NG;
        xo[t] = k * NCOIL + (act ? c : 0);
    }
    #pragma unroll
    for (int j = 0; j < 6; ++j) {
        int k = byi + j - 2;
        if (k < 0) k += NG; else if (k >= NG) k -= NG;
        yo[j] = k * (NG * NCOIL);
    }

    float re = 0.f, im = 0.f;
    if (act) {
        #pragma unroll
        for (int j = 0; j < 6; ++j) {
            const float2* rowp = g_final + yo[j];
            #pragma unroll
            for (int t = 0; t < 3; ++t) {
                float2 g = __ldg(rowp + xo[t]);
                float w = wxl[t] * wyl[j];
                re = fmaf(w, g.x, re);
                im = fmaf(w, g.y, im);
            }
        }
    }
    // combine the two halves (lanes 2c and 2c+1)
    re += __shfl_xor_sync(FULL, re, 1);
    im += __shfl_xor_sync(FULL, im, 1);
    if (act && h == 0) out[c * M_SAMP + m] = make_float2(re, im);
}

// ---------------- launch ----------------
extern "C" void kernel_launch(void* const* d_in, const int* in_sizes, int n_in,
                              void* d_out, int out_size) {
    const float* imr = (const float*)d_in[0];
    const float* imi = (const float*)d_in[1];
    const float* smr = (const float*)d_in[2];
    const float* smi = (const float*)d_in[3];
    const float* kt  = (const float*)d_in[4];

    prep_kernel<<<1, 640>>>();
    fftA_kernel<<<(NCOIL * NH) / 2, 256>>>(imr, imi, smr, smi);   // 1920 CTAs
    fftB_kernel<<<(NCOIL * NG) / 2, 256>>>();                     // 3840 CTAs
    interp_kernel<<<M_SAMP / 8, 256>>>(kt, (float2*)d_out);
}

// round 6
// speedup vs baseline: 3.1063x; 1.1127x over previous
#include <cuda_runtime.h>
#include <math.h>

// ---------------- problem constants ----------------
#define M_SAMP 102400
#define NCOIL  12
#define NG     640          // oversampled grid
#define NH     320          // image size
#define NP     645          // padded grid dim (halo: -2..642)

#define PI_D 3.14159265358979323846
#define BETA_D (PI_D * 4.4102154142094819)   /* pi*sqrt(19.45) */

// padded smem indexing to avoid strided bank conflicts
#define PHYS(i) ((i) + ((i) >> 2))

// ---------------- static device scratch ----------------
__device__ float2 g_final[NP * NP * NCOIL];  // padded final grid [k2+2][kr+2][c] (39.9MB)
__device__ float2 g_mid  [NCOIL * NG * NG];  // after pass A: [c][k2][r]
__device__ float2 g_T128[96];                // W128^k
__device__ float2 g_T640[512];               // W640^e
__device__ float  g_S[NH];                   // apod reciprocal * 1/sqrt(640)

__constant__ float2 c_W5[5] = {
    { 1.0f,                 0.0f                },
    { 0.30901699437494745f,-0.9510565162951535f },
    {-0.80901699437494745f,-0.5877852522924731f },
    {-0.80901699437494745f, 0.5877852522924731f },
    { 0.30901699437494745f, 0.9510565162951535f }
};

__device__ __forceinline__ float2 cmul(float2 a, float2 b) {
    return make_float2(a.x*b.x - a.y*b.y, a.x*b.y + a.y*b.x);
}

// ---------------- kernel 1: tables ----------------
__global__ void prep_kernel() {
    int t = threadIdx.x;   // 640 threads
    if (t < 96) {
        double a = -2.0 * PI_D * (double)t / 128.0;
        g_T128[t] = make_float2((float)cos(a), (float)sin(a));
    }
    if (t < 512) {
        double a = -2.0 * PI_D * (double)t / 640.0;
        g_T640[t] = make_float2((float)cos(a), (float)sin(a));
    }
    if (t < NH) {
        float n = (float)t - 160.0f;
        float acc = 0.0f;
        #pragma unroll
        for (int js = -6; js <= 6; ++js) {
            float m = fabsf((float)js) * (1.0f/3.0f);
            float kv = 0.0f;
            if (m <= 1.0f) {
                float arg = fmaxf(1.0f - m*m, 0.0f);
                kv = cyl_bessel_i0f((float)BETA_D * sqrtf(arg)) * (1.0f/6.0f);
            }
            acc += kv * cosf(2.0f * (float)PI_D * (float)js * n / 640.0f);
        }
        g_S[t] = 1.0f / acc * 0.039528470752104741f;   // 1/sqrt(640)
    }
}

// ---------------- radix-4 Stockham work item ----------------
__device__ __forceinline__ void r4_item(const float2* X, float2* Y, int w, int s) {
    int sub = w >> 5;
    int bb  = w & 31;
    int q   = bb & (s - 1);
    int ps  = bb - q;            // p*s
    int bi  = sub * 128;
    float2 x0 = X[PHYS(bi + bb)];
    float2 x1 = X[PHYS(bi + bb + 32)];
    float2 x2 = X[PHYS(bi + bb + 64)];
    float2 x3 = X[PHYS(bi + bb + 96)];
    float2 A = make_float2(x0.x + x2.x, x0.y + x2.y);
    float2 B = make_float2(x1.x + x3.x, x1.y + x3.y);
    float2 C = make_float2(x0.x - x2.x, x0.y - x2.y);
    float2 D = make_float2(x1.x - x3.x, x1.y - x3.y);
    float2 E = make_float2(D.y, -D.x);              // -i*D
    float2 w1 = g_T128[ps];
    float2 w2 = g_T128[2*ps];
    float2 w3 = g_T128[3*ps];
    int o = bi + 4*ps + q;
    Y[PHYS(o)]       = make_float2(A.x + B.x, A.y + B.y);
    Y[PHYS(o + s)]   = cmul(make_float2(C.x + E.x, C.y + E.y), w1);
    Y[PHYS(o + 2*s)] = cmul(make_float2(A.x - B.x, A.y - B.y), w2);
    Y[PHYS(o + 3*s)] = cmul(make_float2(C.x - E.x, C.y - E.y), w3);
}

// 640-pt FFT on decimated data in A; RESULT left in A (PHYS-indexed, natural order)
__device__ __forceinline__ void fft_line_stage(float2* A, float2* B, int lane) {
    float2 *X = A, *Y = B;
    #pragma unroll
    for (int st = 0; st < 3; ++st) {
        int s = 1 << (2*st);
        r4_item(X, Y, lane, s);
        if (lane < 32) r4_item(X, Y, 128 + lane, s);
        __syncthreads();
        float2* t = X; X = Y; Y = t;
    }
    // after 3 swaps X==B, Y==A: read X, write results into Y (=A)
    int l6 = lane & 63;
    float2 v[5];
    #pragma unroll
    for (int j = 0; j < 5; ++j) {
        float2 u = X[PHYS(j*128 + l6)];
        float2 w = X[PHYS(j*128 + l6 + 64)];
        float2 f = (lane < 64) ? make_float2(u.x + w.x, u.y + w.y)
                               : make_float2(u.x - w.x, u.y - w.y);
        v[j] = cmul(f, g_T640[j * lane]);
    }
    #pragma unroll
    for (int k2 = 0; k2 < 5; ++k2) {
        float2 acc = v[0];
        #pragma unroll
        for (int j = 1; j < 5; ++j) {
            float2 w5 = c_W5[(j * k2) % 5];
            acc.x += v[j].x * w5.x - v[j].y * w5.y;
            acc.y += v[j].x * w5.y + v[j].y * w5.x;
        }
        Y[PHYS(lane + 128 * k2)] = acc;
    }
}

// ---------------- pass A: fused build + column FFT, row-paired float4 store ----------------
__global__ void fftA_kernel(const float* __restrict__ imr, const float* __restrict__ imi,
                            const float* __restrict__ smr, const float* __restrict__ smi) {
    __shared__ float2 SA[2][800];
    __shared__ float2 SB[2][800];
    int tid  = threadIdx.x;
    int lane = tid & 127;
    int ln   = tid >> 7;
    int b    = blockIdx.x;                   // [0, 12*160)
    int coil = b / 160;
    int q    = b - coil * 160;
    int rr   = 2*q + ln;                     // [0,320), pair stays in one half
    int h    = (rr < 160) ? rr + 160 : rr - 160;

    float sh_ = g_S[h];
    const float* smr_c = smr + coil * (NH*NH);
    const float* smi_c = smi + coil * (NH*NH);

    #pragma unroll
    for (int j = 0; j < 5; ++j) {
        int sc = 5 * lane + j;               // shifted column index
        float2 val = make_float2(0.f, 0.f);
        int w = -1;
        if (sc < 160) w = sc + 160;
        else if (sc >= 480) w = sc - 480;
        if (w >= 0) {
            int ii = h * NH + w;
            float ir = imr[ii], ij = imi[ii];
            float sr = smr_c[ii], sj = smi_c[ii];
            float sca = sh_ * g_S[w];
            val.x = (ir*sr - ij*sj) * sca;
            val.y = (ir*sj + ij*sr) * sca;
        }
        SA[ln][PHYS(j*128 + lane)] = val;    // decimated: A[j*128+n1] = x[5*n1+j]
    }
    __syncthreads();
    fft_line_stage(SA[ln], SB[ln], lane);    // result in SA[ln]
    __syncthreads();

    // cooperative float4 store: g_mid[(coil*NG + k2)*NG + r0..r0+1]
    int rr0 = 2*q;
    int r0  = (rr0 < 160) ? rr0 : rr0 + 320;  // even
    float2* gbase = g_mid + coil * (NG*NG) + r0;
    for (int k2 = tid; k2 < NG; k2 += 256) {
        float2 a = SA[0][PHYS(k2)];
        float2 bb = SA[1][PHYS(k2)];
        *reinterpret_cast<float4*>(gbase + k2 * NG) = make_float4(a.x, a.y, bb.x, bb.y);
    }
}

// ---------------- pass B: row FFT, coil-paired float4 store into padded grid ----------------
__global__ void fftB_kernel() {
    __shared__ float2 SA[2][800];
    __shared__ float2 SB[2][800];
    int tid  = threadIdx.x;
    int lane = tid & 127;
    int ln   = tid >> 7;
    int b    = blockIdx.x;                   // [0, 640*6)
    int k2   = b / 6;
    int cp   = b - k2 * 6;
    int coil = 2*cp + ln;
    const float2* gin = g_mid + (coil * NG + k2) * NG;

    #pragma unroll
    for (int j = 0; j < 5; ++j) {
        int sc = 5 * lane + j;
        float2 val = make_float2(0.f, 0.f);
        if (sc < 160 || sc >= 480) val = __ldg(&gin[sc]);
        SA[ln][PHYS(j*128 + lane)] = val;
    }
    __syncthreads();
    fft_line_stage(SA[ln], SB[ln], lane);    // result in SA[ln]
    __syncthreads();

    // cooperative float4 store: g_final[((k2+2)*NP + kr+2)*NCOIL + 2cp..2cp+1]
    float2* gbase = g_final + ((k2 + 2) * NP + 2) * NCOIL + 2*cp;
    for (int kr = tid; kr < NG; kr += 256) {
        float2 a = SA[0][PHYS(kr)];
        float2 bb = SA[1][PHYS(kr)];
        *reinterpret_cast<float4*>(gbase + kr * NCOIL) = make_float4(a.x, a.y, bb.x, bb.y);
    }
}

// ---------------- halo fill: wrap-copy interior into padded borders ----------------
// padded cell (yp, xp) outside interior <- interior at wrapped coords. 6425 halo cells.
__global__ void halo_kernel() {
    int cell = blockIdx.x * 256 + threadIdx.x;
    if (cell >= 6425) return;
    int yp, xp;
    if (cell < 1290) {                 // top 2 full rows
        yp = cell / NP; xp = cell - yp * NP;
    } else if (cell < 3225) {          // bottom 3 full rows
        int c2 = cell - 1290;
        yp = 642 + c2 / NP; xp = c2 - (c2 / NP) * NP;
    } else {                           // middle 640 rows x 5 halo cols
        int c3 = cell - 3225;
        yp = 2 + c3 / 5;
        int qq = c3 - (c3 / 5) * 5;
        xp = (qq < 2) ? qq : 640 + qq;
    }
    int ys = yp - 2; if (ys < 0) ys += 640; else if (ys >= 640) ys -= 640;
    int xs = xp - 2; if (xs < 0) xs += 640; else if (xs >= 640) xs -= 640;
    const float4* src = reinterpret_cast<const float4*>(g_final + ((ys+2) * NP + (xs+2)) * NCOIL);
    float4*       dst = reinterpret_cast<float4*>(g_final + (yp * NP + xp) * NCOIL);
    #pragma unroll
    for (int i = 0; i < 6; ++i) dst[i] = src[i];
}

// ---------------- KB interpolation: warp per sample, halo grid, immediate offsets ----------------
__global__ void interp_kernel(const float* __restrict__ kt, float2* __restrict__ out) {
    int m    = blockIdx.x * 8 + (threadIdx.x >> 5);
    int lane = threadIdx.x & 31;

    const float BETA_F = (float)BETA_D;
    const float G2PI   = 101.85916357881302f;   // 640/(2*pi)
    const unsigned FULL = 0xffffffffu;

    float om1 = __ldg(kt + m);
    float om2 = __ldg(kt + M_SAMP + m);
    float tx = om1 * G2PI; if (tx < 0.f) tx += 640.f;
    float ty = om2 * G2PI; if (ty < 0.f) ty += 640.f;
    float bx = floorf(tx), by = floorf(ty);

    // KB kernel values: lanes 0..5 -> x taps, 6..11 -> y taps
    float kv = 0.f;
    if (lane < 12) {
        bool isx = lane < 6;
        int  sl  = isx ? lane : lane - 6;
        float t  = isx ? tx : ty;
        float bqq= isx ? bx : by;
        float u  = t - (bqq + (float)(sl - 2));
        float mm = fabsf(u) * (1.f/3.f);
        float arg = fmaxf(1.f - mm*mm, 0.f);
        kv = (mm <= 1.f) ? cyl_bessel_i0f(BETA_F * sqrtf(arg)) * (1.f/6.f) : 0.f;
    }

    int c   = lane >> 1;          // coil
    int h   = lane & 1;           // x half: taps h*3..h*3+2
    bool act = (lane < 24);

    float wxl[3], wyl[6];
    #pragma unroll
    for (int t = 0; t < 3; ++t) wxl[t] = __shfl_sync(FULL, kv, h*3 + t);
    #pragma unroll
    for (int j = 0; j < 6; ++j) wyl[j] = __shfl_sync(FULL, kv, 6 + j);

    // base: padded grid, tap (t',j) at base + j*NP*12 + t'*12 (t' = h*3+t)
    int bxi = (int)bx, byi = (int)by;
    const float2* p = g_final + (byi * NP + bxi) * NCOIL + (act ? (c + h*36) : 0);

    float re = 0.f, im = 0.f;
    if (act) {
        #pragma unroll
        for (int j = 0; j < 6; ++j) {
            #pragma unroll
            for (int t = 0; t < 3; ++t) {
                float2 g = __ldg(p + j * (NP*NCOIL) + t * NCOIL);
                float w = wxl[t] * wyl[j];
                re = fmaf(w, g.x, re);
                im = fmaf(w, g.y, im);
            }
        }
    }
    re += __shfl_xor_sync(FULL, re, 1);
    im += __shfl_xor_sync(FULL, im, 1);
    if (act && h == 0) out[c * M_SAMP + m] = make_float2(re, im);
}

// ---------------- launch ----------------
extern "C" void kernel_launch(void* const* d_in, const int* in_sizes, int n_in,
                              void* d_out, int out_size) {
    const float* imr = (const float*)d_in[0];
    const float* imi = (const float*)d_in[1];
    const float* smr = (const float*)d_in[2];
    const float* smi = (const float*)d_in[3];
    const float* kt  = (const float*)d_in[4];

    prep_kernel<<<1, 640>>>();
    fftA_kernel<<<NCOIL * 160, 256>>>(imr, imi, smr, smi);   // 1920 CTAs, 2 rows each
    fftB_kernel<<<NG * 6, 256>>>();                          // 3840 CTAs, 2 coils each
    halo_kernel<<<26, 256>>>();
    interp_kernel<<<M_SAMP / 8, 256>>>(kt, (float2*)d_out);
}